// round 11
// baseline (speedup 1.0000x reference)
#include <cuda_runtime.h>
#include <cuda_fp16.h>
#include <math.h>
#include <stdint.h>

#define BB    64
#define TT    256
#define IDIM  512
#define HDIM  1024
#define G4    4096        // 4*HDIM
#define GRID  128         // persistent blocks (<=148, all resident)
#define HROW  72          // padded sub-buffer row stride in halfs (64 data + 8 pad)
#define SUBSZ (64 * HROW) // halfs per 64x64 sub-buffer
#define NSUB  16          // sub-buffers = full K=1024, single-buffered

// ---- device scratch ----
__device__ float    g_gates[(size_t)TT * BB * G4];  // [T][B][4H], bi+bh folded in
__device__ __half   g_h[2][BB * HDIM];              // double-buffered hidden state (fp16)
__device__ unsigned g_arrive;
__device__ unsigned g_gen;

// ---------------------------------------------------------------------------
// helpers
// ---------------------------------------------------------------------------
__device__ __forceinline__ float tf32r(float v) {
    uint32_t u;
    asm("cvt.rna.tf32.f32 %0, %1;" : "=r"(u) : "f"(v));
    return __uint_as_float(u);
}

__device__ __forceinline__ void mma_tf32(float d[4],
    uint32_t a0, uint32_t a1, uint32_t a2, uint32_t a3,
    uint32_t b0, uint32_t b1)
{
    asm volatile(
        "mma.sync.aligned.m16n8k8.row.col.f32.tf32.tf32.f32 "
        "{%0,%1,%2,%3},{%4,%5,%6,%7},{%8,%9},{%0,%1,%2,%3};\n"
        : "+f"(d[0]), "+f"(d[1]), "+f"(d[2]), "+f"(d[3])
        : "r"(a0), "r"(a1), "r"(a2), "r"(a3), "r"(b0), "r"(b1));
}

__device__ __forceinline__ void mma_f16(float d[4],
    uint32_t a0, uint32_t a1, uint32_t a2, uint32_t a3,
    uint32_t b0, uint32_t b1)
{
    asm volatile(
        "mma.sync.aligned.m16n8k16.row.col.f32.f16.f16.f32 "
        "{%0,%1,%2,%3},{%4,%5,%6,%7},{%8,%9},{%0,%1,%2,%3};\n"
        : "+f"(d[0]), "+f"(d[1]), "+f"(d[2]), "+f"(d[3])
        : "r"(a0), "r"(a1), "r"(a2), "r"(a3), "r"(b0), "r"(b1));
}

__device__ __forceinline__ float sigf(float x) {
    return 1.f / (1.f + __expf(-x));
}

// ---------------------------------------------------------------------------
// Phase 1: gates = x @ Wi + bi + bh   (tf32 MMA, unchanged/proven)
// ---------------------------------------------------------------------------
__global__ void __launch_bounds__(256, 2) gemm_tc_kernel(
    const float* __restrict__ X,
    const float* __restrict__ Wi,
    const float* __restrict__ bi,
    const float* __restrict__ bh)
{
    if (blockIdx.x == 0 && blockIdx.y == 0 && threadIdx.x == 0) {
        g_arrive = 0u;
        g_gen    = 0u;
    }

    __shared__ float As[16][132];
    __shared__ float Bs[16][132];

    const int tid  = threadIdx.x;
    const int lane = tid & 31;
    const int w    = tid >> 5;
    const int wm   = w & 1;
    const int wn   = w >> 1;
    const int m0   = blockIdx.y * 128;
    const int n0   = blockIdx.x * 128;

    const int rowg = lane >> 2;
    const int kq   = lane & 3;

    const int aRow = tid >> 1;
    const int aCol = (tid & 1) * 8;
    const int bRow = tid >> 5;
    const int bCol = (tid & 31) * 4;

    float acc[4][4][4];
#pragma unroll
    for (int mi = 0; mi < 4; mi++)
#pragma unroll
        for (int ni = 0; ni < 4; ni++)
#pragma unroll
            for (int q = 0; q < 4; q++) acc[mi][ni][q] = 0.f;

    float4 pa0 = *(const float4*)(X + (size_t)(m0 + aRow) * IDIM + aCol);
    float4 pa1 = *(const float4*)(X + (size_t)(m0 + aRow) * IDIM + aCol + 4);
    float4 pb0 = *(const float4*)(Wi + (size_t)bRow * G4 + n0 + bCol);
    float4 pb1 = *(const float4*)(Wi + (size_t)(bRow + 8) * G4 + n0 + bCol);

    for (int k0 = 0; k0 < IDIM; k0 += 16) {
        As[aCol + 0][aRow] = tf32r(pa0.x);
        As[aCol + 1][aRow] = tf32r(pa0.y);
        As[aCol + 2][aRow] = tf32r(pa0.z);
        As[aCol + 3][aRow] = tf32r(pa0.w);
        As[aCol + 4][aRow] = tf32r(pa1.x);
        As[aCol + 5][aRow] = tf32r(pa1.y);
        As[aCol + 6][aRow] = tf32r(pa1.z);
        As[aCol + 7][aRow] = tf32r(pa1.w);
        {
            float4 b0 = pb0, b1 = pb1;
            b0.x = tf32r(b0.x); b0.y = tf32r(b0.y); b0.z = tf32r(b0.z); b0.w = tf32r(b0.w);
            b1.x = tf32r(b1.x); b1.y = tf32r(b1.y); b1.z = tf32r(b1.z); b1.w = tf32r(b1.w);
            *(float4*)(&Bs[bRow][bCol])     = b0;
            *(float4*)(&Bs[bRow + 8][bCol]) = b1;
        }
        __syncthreads();

        if (k0 + 16 < IDIM) {
            int kn = k0 + 16;
            pa0 = *(const float4*)(X + (size_t)(m0 + aRow) * IDIM + kn + aCol);
            pa1 = *(const float4*)(X + (size_t)(m0 + aRow) * IDIM + kn + aCol + 4);
            pb0 = *(const float4*)(Wi + (size_t)(kn + bRow) * G4 + n0 + bCol);
            pb1 = *(const float4*)(Wi + (size_t)(kn + bRow + 8) * G4 + n0 + bCol);
        }

#pragma unroll
        for (int ks = 0; ks < 2; ks++) {
            const int kb = ks * 8;
            uint32_t af[4][4], bf[4][2];
#pragma unroll
            for (int mi = 0; mi < 4; mi++) {
                int r = wm * 64 + mi * 16 + rowg;
                af[mi][0] = __float_as_uint(As[kb + kq][r]);
                af[mi][1] = __float_as_uint(As[kb + kq][r + 8]);
                af[mi][2] = __float_as_uint(As[kb + kq + 4][r]);
                af[mi][3] = __float_as_uint(As[kb + kq + 4][r + 8]);
            }
#pragma unroll
            for (int ni = 0; ni < 4; ni++) {
                int c = wn * 32 + ni * 8 + rowg;
                bf[ni][0] = __float_as_uint(Bs[kb + kq][c]);
                bf[ni][1] = __float_as_uint(Bs[kb + kq + 4][c]);
            }
#pragma unroll
            for (int mi = 0; mi < 4; mi++)
#pragma unroll
                for (int ni = 0; ni < 4; ni++)
                    mma_tf32(acc[mi][ni], af[mi][0], af[mi][1], af[mi][2], af[mi][3],
                             bf[ni][0], bf[ni][1]);
        }
        __syncthreads();
    }

#pragma unroll
    for (int ni = 0; ni < 4; ni++) {
        int n = n0 + wn * 32 + ni * 8 + 2 * kq;
        float bias0 = bi[n] + bh[n];
        float bias1 = bi[n + 1] + bh[n + 1];
#pragma unroll
        for (int mi = 0; mi < 4; mi++) {
            int m  = m0 + wm * 64 + mi * 16 + rowg;
            {
                int b = m >> 8, t = m & 255;
                float2 v = make_float2(acc[mi][ni][0] + bias0, acc[mi][ni][1] + bias1);
                *(float2*)(g_gates + (size_t)(t * BB + b) * G4 + n) = v;
            }
            {
                int m2 = m + 8;
                int b = m2 >> 8, t = m2 & 255;
                float2 v = make_float2(acc[mi][ni][2] + bias0, acc[mi][ni][3] + bias1);
                *(float2*)(g_gates + (size_t)(t * BB + b) * G4 + n) = v;
            }
        }
    }
}

// ---------------------------------------------------------------------------
// Phase 2: persistent LSTM recurrence (fp16 mma).
// ONLY change vs R10: stage the ENTIRE h tile (16 sub-buffers, single-
// buffered) per step -> 2 block syncs per step, 64 uninterrupted mma k-steps.
// ---------------------------------------------------------------------------
__global__ void __launch_bounds__(256, 1) lstm_persist_kernel(
    const float* __restrict__ Wh,   // [1024, 4096]
    float* __restrict__ out)        // Q_all | hT | cT
{
    extern __shared__ char smem[];
    uint2*  Wf = (uint2*)smem;                       // [64 s][4 ct][32 lanes] = 64 KB
    __half* Hs = (__half*)(smem + 65536);            // NSUB * SUBSZ halfs (147,456 B)

    const int tid  = threadIdx.x;
    const int lane = tid & 31;
    const int wid  = tid >> 5;
    const int wm   = wid & 3;
    const int wn   = wid >> 2;
    const int bx   = blockIdx.x;

    // build Wf (fp16 B-fragments for m16n8k16), once -- identical to R8/R10
    for (int e = tid; e < 64 * 4 * 32; e += 256) {
        int l  = e & 31;
        int ct = (e >> 5) & 3;
        int s  = e >> 7;
        int k  = s * 16 + (l & 3) * 2;
        int n  = ct * 8 + (l >> 2);
        int j  = bx * 8 + (n >> 2);
        int g  = n & 3;
        const float* Wcol = Wh + (size_t)g * 1024 + j;
        __half2 h0 = __floats2half2_rn(Wcol[(size_t)k * G4],
                                       Wcol[(size_t)(k + 1) * G4]);
        __half2 h1 = __floats2half2_rn(Wcol[(size_t)(k + 8) * G4],
                                       Wcol[(size_t)(k + 9) * G4]);
        uint2 v;
        v.x = *(uint32_t*)&h0;
        v.y = *(uint32_t*)&h1;
        Wf[e] = v;
    }
    __syncthreads();

    const int kq   = lane & 3;
    const int rowg = lane >> 2;
    const int odd  = lane & 1;
    const int bmy  = wm * 16 + rowg + (odd ? 8 : 0);
    const int jbase = bx * 8 + wn * 4 + (kq >> 1);

    float creg[2] = {0.f, 0.f};
    const int arow = wm * 16 + rowg;

    // staging indices: rows {sb, sb+32}, 16B group sg within each 64-col sub
    const int sb = tid >> 3;     // 0..31
    const int sg = tid & 7;      // 0..7

    for (int t = 0; t < TT; t++) {
        float acc[2][4] = {{0.f,0.f,0.f,0.f},{0.f,0.f,0.f,0.f}};

        const float* __restrict__ gt = g_gates + (size_t)t * BB * G4;
        float gF[2], gI[2], gA[2], gO[2];
#pragma unroll
        for (int nt = 0; nt < 2; nt++) {
            int j = jbase + nt * 2;
            gF[nt] = __ldcg(gt + (size_t)bmy * G4 + j);
            gI[nt] = __ldcg(gt + (size_t)bmy * G4 + 1024 + j);
            gA[nt] = __ldcg(gt + (size_t)bmy * G4 + 2048 + j);
            gO[nt] = __ldcg(gt + (size_t)bmy * G4 + 3072 + j);
        }

        if (t > 0) {
            // ---- grid barrier (proven form) ----
            __threadfence();
            __syncthreads();
            if (tid == 0) {
                unsigned a = atomicAdd(&g_arrive, 1u);
                if (a == GRID - 1u) {
                    g_arrive = 0u;
                    __threadfence();
                    atomicExch(&g_gen, (unsigned)t);
                } else {
                    while (atomicAdd(&g_gen, 0u) < (unsigned)t) { }
                }
            }
            __syncthreads();

            const __half* __restrict__ hin = g_h[t & 1];

            // ---- stage the FULL h tile: 4 batches of pf[2][4], no syncs ----
#pragma unroll
            for (int bt = 0; bt < 4; bt++) {
                uint4 pf[2][4];
                int kb = bt * 256;
#pragma unroll
                for (int i = 0; i < 2; i++) {
                    int b = sb + i * 32;
#pragma unroll
                    for (int q = 0; q < 4; q++)
                        pf[i][q] = __ldcg((const uint4*)(hin + (size_t)b * HDIM
                                                         + kb + q * 64 + sg * 8));
                }
#pragma unroll
                for (int i = 0; i < 2; i++) {
                    int b = sb + i * 32;
#pragma unroll
                    for (int q = 0; q < 4; q++)
                        *(uint4*)(Hs + (bt * 4 + q) * SUBSZ + b * HROW + sg * 8)
                            = pf[i][q];
                }
            }
            __syncthreads();   // staging complete -> mma may read

            // ---- 64 uninterrupted fp16 mma k-steps over the full K ----
            const __half* Hbase = Hs + arow * HROW;
#pragma unroll
            for (int ks = 0; ks < 64; ks++) {
                int q   = ks >> 2;
                int kss = ks & 3;
                const __half* H = Hbase + q * SUBSZ;
                int col = kss * 16 + kq * 2;
                uint32_t a0 = *(const uint32_t*)(H + col);
                uint32_t a1 = *(const uint32_t*)(H + 8 * HROW + col);
                uint32_t a2 = *(const uint32_t*)(H + col + 8);
                uint32_t a3 = *(const uint32_t*)(H + 8 * HROW + col + 8);
#pragma unroll
                for (int nt = 0; nt < 2; nt++) {
                    uint2 bv = Wf[(ks * 4 + wn * 2 + nt) * 32 + lane];
                    mma_f16(acc[nt], a0, a1, a2, a3, bv.x, bv.y);
                }
            }
            __syncthreads();   // all reads done before next step's staging
        }

        // ---- epilogue (unchanged) ----
        __half* __restrict__ hout = g_h[(t + 1) & 1];
#pragma unroll
        for (int nt = 0; nt < 2; nt++) {
            float x0 = __shfl_xor_sync(0xffffffffu, acc[nt][0], 1);
            float x1 = __shfl_xor_sync(0xffffffffu, acc[nt][1], 1);
            float x2 = __shfl_xor_sync(0xffffffffu, acc[nt][2], 1);
            float x3 = __shfl_xor_sync(0xffffffffu, acc[nt][3], 1);

            float F, I, A, O;
            if (!odd) { F = acc[nt][0]; I = acc[nt][1]; A = x0; O = x1; }
            else      { F = x2;         I = x3;         A = acc[nt][2]; O = acc[nt][3]; }

            F += gF[nt]; I += gI[nt]; A += gA[nt]; O += gO[nt];

            float f = sigf(F);
            float i = sigf(I);
            float a = tanhf(A);
            float o = sigf(O);

            float c = f * creg[nt] + i * a;
            creg[nt] = c;
            float h = o * tanhf(c);

            int j = jbase + nt * 2;
            hout[(size_t)bmy * HDIM + j] = __float2half(h);
            out[((size_t)bmy * TT + t) * HDIM + j] = h;
            if (t == TT - 1) {
                size_t qsz = (size_t)BB * TT * HDIM;
                out[qsz + (size_t)bmy * HDIM + j]             = h;
                out[qsz + BB * HDIM + (size_t)bmy * HDIM + j] = c;
            }
        }
    }
}

// ---------------------------------------------------------------------------
extern "C" void kernel_launch(void* const* d_in, const int* in_sizes, int n_in,
                              void* d_out, int out_size) {
    const float* x  = (const float*)d_in[0];
    const float* Wi = (const float*)d_in[1];
    const float* bi = (const float*)d_in[2];
    const float* Wh = (const float*)d_in[3];
    const float* bh = (const float*)d_in[4];
    float* out = (float*)d_out;

    const int smem_bytes = 65536 + NSUB * SUBSZ * 2;   // 212,992 B
    cudaFuncSetAttribute(lstm_persist_kernel,
                         cudaFuncAttributeMaxDynamicSharedMemorySize, smem_bytes);

    gemm_tc_kernel<<<dim3(G4 / 128, (BB * TT) / 128), 256>>>(x, Wi, bi, bh);
    lstm_persist_kernel<<<GRID, 256, smem_bytes>>>(Wh, out);
}

// round 12
// speedup vs baseline: 1.0655x; 1.0655x over previous
#include <cuda_runtime.h>
#include <cuda_fp16.h>
#include <math.h>
#include <stdint.h>

#define BB    64
#define TT    256
#define IDIM  512
#define HDIM  1024
#define G4    4096        // 4*HDIM
#define GRID  128         // persistent blocks (<=148, all resident)
#define HROW  72          // padded sub-buffer row stride in halfs (64 data + 8 pad)
#define SUBSZ (64 * HROW) // halfs per 64x64 sub-buffer
#define CKB   256         // staging chunk width in halfs (4 sub-buffers)

// ---- device scratch ----
__device__ float    g_gates[(size_t)TT * BB * G4];  // [T][B][4H], bi+bh folded in
__device__ __half   g_h[2][BB * HDIM];              // double-buffered hidden state (fp16)
__device__ unsigned g_arrive;
__device__ unsigned g_gen;

// ---------------------------------------------------------------------------
// helpers
// ---------------------------------------------------------------------------
__device__ __forceinline__ float tf32r(float v) {
    uint32_t u;
    asm("cvt.rna.tf32.f32 %0, %1;" : "=r"(u) : "f"(v));
    return __uint_as_float(u);
}

__device__ __forceinline__ void mma_tf32(float d[4],
    uint32_t a0, uint32_t a1, uint32_t a2, uint32_t a3,
    uint32_t b0, uint32_t b1)
{
    asm volatile(
        "mma.sync.aligned.m16n8k8.row.col.f32.tf32.tf32.f32 "
        "{%0,%1,%2,%3},{%4,%5,%6,%7},{%8,%9},{%0,%1,%2,%3};\n"
        : "+f"(d[0]), "+f"(d[1]), "+f"(d[2]), "+f"(d[3])
        : "r"(a0), "r"(a1), "r"(a2), "r"(a3), "r"(b0), "r"(b1));
}

__device__ __forceinline__ void mma_f16(float d[4],
    uint32_t a0, uint32_t a1, uint32_t a2, uint32_t a3,
    uint32_t b0, uint32_t b1)
{
    asm volatile(
        "mma.sync.aligned.m16n8k16.row.col.f32.f16.f16.f32 "
        "{%0,%1,%2,%3},{%4,%5,%6,%7},{%8,%9},{%0,%1,%2,%3};\n"
        : "+f"(d[0]), "+f"(d[1]), "+f"(d[2]), "+f"(d[3])
        : "r"(a0), "r"(a1), "r"(a2), "r"(a3), "r"(b0), "r"(b1));
}

__device__ __forceinline__ void ldsm_x4(uint32_t& r0, uint32_t& r1,
                                        uint32_t& r2, uint32_t& r3,
                                        uint32_t smem_addr)
{
    asm volatile(
        "ldmatrix.sync.aligned.m8n8.x4.shared.b16 {%0,%1,%2,%3}, [%4];"
        : "=r"(r0), "=r"(r1), "=r"(r2), "=r"(r3)
        : "r"(smem_addr));
}

__device__ __forceinline__ float sigf(float x) {
    return 1.f / (1.f + __expf(-x));
}

// ---------------------------------------------------------------------------
// Phase 1: gates = x @ Wi + bi + bh   (tf32 MMA, unchanged/proven)
// ---------------------------------------------------------------------------
__global__ void __launch_bounds__(256, 2) gemm_tc_kernel(
    const float* __restrict__ X,
    const float* __restrict__ Wi,
    const float* __restrict__ bi,
    const float* __restrict__ bh)
{
    if (blockIdx.x == 0 && blockIdx.y == 0 && threadIdx.x == 0) {
        g_arrive = 0u;
        g_gen    = 0u;
    }

    __shared__ float As[16][132];
    __shared__ float Bs[16][132];

    const int tid  = threadIdx.x;
    const int lane = tid & 31;
    const int w    = tid >> 5;
    const int wm   = w & 1;
    const int wn   = w >> 1;
    const int m0   = blockIdx.y * 128;
    const int n0   = blockIdx.x * 128;

    const int rowg = lane >> 2;
    const int kq   = lane & 3;

    const int aRow = tid >> 1;
    const int aCol = (tid & 1) * 8;
    const int bRow = tid >> 5;
    const int bCol = (tid & 31) * 4;

    float acc[4][4][4];
#pragma unroll
    for (int mi = 0; mi < 4; mi++)
#pragma unroll
        for (int ni = 0; ni < 4; ni++)
#pragma unroll
            for (int q = 0; q < 4; q++) acc[mi][ni][q] = 0.f;

    float4 pa0 = *(const float4*)(X + (size_t)(m0 + aRow) * IDIM + aCol);
    float4 pa1 = *(const float4*)(X + (size_t)(m0 + aRow) * IDIM + aCol + 4);
    float4 pb0 = *(const float4*)(Wi + (size_t)bRow * G4 + n0 + bCol);
    float4 pb1 = *(const float4*)(Wi + (size_t)(bRow + 8) * G4 + n0 + bCol);

    for (int k0 = 0; k0 < IDIM; k0 += 16) {
        As[aCol + 0][aRow] = tf32r(pa0.x);
        As[aCol + 1][aRow] = tf32r(pa0.y);
        As[aCol + 2][aRow] = tf32r(pa0.z);
        As[aCol + 3][aRow] = tf32r(pa0.w);
        As[aCol + 4][aRow] = tf32r(pa1.x);
        As[aCol + 5][aRow] = tf32r(pa1.y);
        As[aCol + 6][aRow] = tf32r(pa1.z);
        As[aCol + 7][aRow] = tf32r(pa1.w);
        {
            float4 b0 = pb0, b1 = pb1;
            b0.x = tf32r(b0.x); b0.y = tf32r(b0.y); b0.z = tf32r(b0.z); b0.w = tf32r(b0.w);
            b1.x = tf32r(b1.x); b1.y = tf32r(b1.y); b1.z = tf32r(b1.z); b1.w = tf32r(b1.w);
            *(float4*)(&Bs[bRow][bCol])     = b0;
            *(float4*)(&Bs[bRow + 8][bCol]) = b1;
        }
        __syncthreads();

        if (k0 + 16 < IDIM) {
            int kn = k0 + 16;
            pa0 = *(const float4*)(X + (size_t)(m0 + aRow) * IDIM + kn + aCol);
            pa1 = *(const float4*)(X + (size_t)(m0 + aRow) * IDIM + kn + aCol + 4);
            pb0 = *(const float4*)(Wi + (size_t)(kn + bRow) * G4 + n0 + bCol);
            pb1 = *(const float4*)(Wi + (size_t)(kn + bRow + 8) * G4 + n0 + bCol);
        }

#pragma unroll
        for (int ks = 0; ks < 2; ks++) {
            const int kb = ks * 8;
            uint32_t af[4][4], bf[4][2];
#pragma unroll
            for (int mi = 0; mi < 4; mi++) {
                int r = wm * 64 + mi * 16 + rowg;
                af[mi][0] = __float_as_uint(As[kb + kq][r]);
                af[mi][1] = __float_as_uint(As[kb + kq][r + 8]);
                af[mi][2] = __float_as_uint(As[kb + kq + 4][r]);
                af[mi][3] = __float_as_uint(As[kb + kq + 4][r + 8]);
            }
#pragma unroll
            for (int ni = 0; ni < 4; ni++) {
                int c = wn * 32 + ni * 8 + rowg;
                bf[ni][0] = __float_as_uint(Bs[kb + kq][c]);
                bf[ni][1] = __float_as_uint(Bs[kb + kq + 4][c]);
            }
#pragma unroll
            for (int mi = 0; mi < 4; mi++)
#pragma unroll
                for (int ni = 0; ni < 4; ni++)
                    mma_tf32(acc[mi][ni], af[mi][0], af[mi][1], af[mi][2], af[mi][3],
                             bf[ni][0], bf[ni][1]);
        }
        __syncthreads();
    }

#pragma unroll
    for (int ni = 0; ni < 4; ni++) {
        int n = n0 + wn * 32 + ni * 8 + 2 * kq;
        float bias0 = bi[n] + bh[n];
        float bias1 = bi[n + 1] + bh[n + 1];
#pragma unroll
        for (int mi = 0; mi < 4; mi++) {
            int m  = m0 + wm * 64 + mi * 16 + rowg;
            {
                int b = m >> 8, t = m & 255;
                float2 v = make_float2(acc[mi][ni][0] + bias0, acc[mi][ni][1] + bias1);
                *(float2*)(g_gates + (size_t)(t * BB + b) * G4 + n) = v;
            }
            {
                int m2 = m + 8;
                int b = m2 >> 8, t = m2 & 255;
                float2 v = make_float2(acc[mi][ni][2] + bias0, acc[mi][ni][3] + bias1);
                *(float2*)(g_gates + (size_t)(t * BB + b) * G4 + n) = v;
            }
        }
    }
}

// ---------------------------------------------------------------------------
// Phase 2: persistent LSTM recurrence (fp16 mma, R10 skeleton: 4 double-
// buffered 256-col chunks, 4 syncs/step).
// Changes vs R10 (LDS-issue reduction only; identical values/order):
//   * A fragments loaded via ldmatrix.x4 (1 LDSM instead of 4 LDS.32)
//   * Wf repacked as uint4 (1 LDS.128 instead of 2 LDS.64 per k-step)
// ---------------------------------------------------------------------------
__global__ void __launch_bounds__(256, 1) lstm_persist_kernel(
    const float* __restrict__ Wh,   // [1024, 4096]
    float* __restrict__ out)        // Q_all | hT | cT
{
    extern __shared__ char smem[];
    uint4*  Wfq = (uint4*)smem;                      // [64 s][2 wn][32 lanes] = 64 KB
    __half* Hs  = (__half*)(smem + 65536);           // 2 * 4 * SUBSZ halfs (73,728 B)

    const int tid  = threadIdx.x;
    const int lane = tid & 31;
    const int wid  = tid >> 5;
    const int wm   = wid & 3;
    const int wn   = wid >> 2;
    const int bx   = blockIdx.x;

    // build Wfq: same values as R10's Wf, packed {ct=2wn, ct=2wn+1} per uint4
    for (int e = tid; e < 64 * 2 * 32; e += 256) {
        int l  = e & 31;
        int w2 = (e >> 5) & 1;
        int s  = e >> 6;
        int k  = s * 16 + (l & 3) * 2;
        uint32_t vals[4];
#pragma unroll
        for (int nt = 0; nt < 2; nt++) {
            int ct = w2 * 2 + nt;
            int n  = ct * 8 + (l >> 2);
            int j  = bx * 8 + (n >> 2);
            int g  = n & 3;
            const float* Wcol = Wh + (size_t)g * 1024 + j;
            __half2 h0 = __floats2half2_rn(Wcol[(size_t)k * G4],
                                           Wcol[(size_t)(k + 1) * G4]);
            __half2 h1 = __floats2half2_rn(Wcol[(size_t)(k + 8) * G4],
                                           Wcol[(size_t)(k + 9) * G4]);
            vals[nt * 2]     = *(uint32_t*)&h0;
            vals[nt * 2 + 1] = *(uint32_t*)&h1;
        }
        Wfq[e] = make_uint4(vals[0], vals[1], vals[2], vals[3]);
    }
    __syncthreads();

    const int kq   = lane & 3;
    const int rowg = lane >> 2;
    const int odd  = lane & 1;
    const int bmy  = wm * 16 + rowg + (odd ? 8 : 0);
    const int jbase = bx * 8 + wn * 4 + (kq >> 1);

    float creg[2] = {0.f, 0.f};

    // ldmatrix lane base address (bytes, shared space):
    //   row = wm*16 + (lane&15); +16B column offset for lanes 16..31
    const uint32_t hsB = (uint32_t)__cvta_generic_to_shared(Hs);
    const uint32_t laneA = hsB
        + (uint32_t)((wm * 16 + (lane & 15)) * HROW) * 2
        + ((lane & 16) ? 16u : 0u);

    // staging indices: rows {sb, sb+32}, 16B group sg within each 64-col sub
    const int sb = tid >> 3;     // 0..31
    const int sg = tid & 7;      // 0..7

    for (int t = 0; t < TT; t++) {
        float acc[2][4] = {{0.f,0.f,0.f,0.f},{0.f,0.f,0.f,0.f}};

        const float* __restrict__ gt = g_gates + (size_t)t * BB * G4;
        float gF[2], gI[2], gA[2], gO[2];
#pragma unroll
        for (int nt = 0; nt < 2; nt++) {
            int j = jbase + nt * 2;
            gF[nt] = __ldcg(gt + (size_t)bmy * G4 + j);
            gI[nt] = __ldcg(gt + (size_t)bmy * G4 + 1024 + j);
            gA[nt] = __ldcg(gt + (size_t)bmy * G4 + 2048 + j);
            gO[nt] = __ldcg(gt + (size_t)bmy * G4 + 3072 + j);
        }

        if (t > 0) {
            // ---- grid barrier (proven form) ----
            __threadfence();
            __syncthreads();
            if (tid == 0) {
                unsigned a = atomicAdd(&g_arrive, 1u);
                if (a == GRID - 1u) {
                    g_arrive = 0u;
                    __threadfence();
                    atomicExch(&g_gen, (unsigned)t);
                } else {
                    while (atomicAdd(&g_gen, 0u) < (unsigned)t) { }
                }
            }
            __syncthreads();

            const __half* __restrict__ hin = g_h[t & 1];

            // prefetch chunk 0: 8 x uint4 per thread (2 rows x 4 sub-blocks)
            uint4 pf[2][4];
#pragma unroll
            for (int i = 0; i < 2; i++) {
                int b = sb + i * 32;
#pragma unroll
                for (int q = 0; q < 4; q++)
                    pf[i][q] = __ldcg((const uint4*)(hin + (size_t)b * HDIM
                                                     + q * 64 + sg * 8));
            }

            int buf = 0;
            for (int ch = 0; ch < 4; ch++) {
                // store chunk: each uint4 into its 64x72 sub-buffer
                {
                    __half* H = Hs + buf * (4 * SUBSZ);
#pragma unroll
                    for (int i = 0; i < 2; i++) {
                        int b = sb + i * 32;
#pragma unroll
                        for (int q = 0; q < 4; q++)
                            *(uint4*)(H + q * SUBSZ + b * HROW + sg * 8) = pf[i][q];
                    }
                }
                __syncthreads();

                // prefetch next chunk
                if (ch < 3) {
                    int k0 = (ch + 1) * CKB;
#pragma unroll
                    for (int i = 0; i < 2; i++) {
                        int b = sb + i * 32;
#pragma unroll
                        for (int q = 0; q < 4; q++)
                            pf[i][q] = __ldcg((const uint4*)(hin + (size_t)b * HDIM
                                                             + k0 + q * 64 + sg * 8));
                    }
                }

                // 16 fp16 mma k-steps: 1 LDSM.x4 + 1 LDS.128 + 2 HMMA each
                const uint32_t chunkA = laneA + (uint32_t)(buf * (4 * SUBSZ * 2));
#pragma unroll
                for (int ks = 0; ks < 16; ks++) {
                    int q   = ks >> 2;
                    int kss = ks & 3;
                    uint32_t a0, a1, a2, a3;
                    ldsm_x4(a0, a1, a2, a3,
                            chunkA + (uint32_t)(q * (SUBSZ * 2) + kss * 32));
                    int s = ch * 16 + ks;
                    uint4 bv = Wfq[(s * 2 + wn) * 32 + lane];
                    mma_f16(acc[0], a0, a1, a2, a3, bv.x, bv.y);
                    mma_f16(acc[1], a0, a1, a2, a3, bv.z, bv.w);
                }
                buf ^= 1;
            }
            __syncthreads();
        }

        // ---- epilogue (unchanged) ----
        __half* __restrict__ hout = g_h[(t + 1) & 1];
#pragma unroll
        for (int nt = 0; nt < 2; nt++) {
            float x0 = __shfl_xor_sync(0xffffffffu, acc[nt][0], 1);
            float x1 = __shfl_xor_sync(0xffffffffu, acc[nt][1], 1);
            float x2 = __shfl_xor_sync(0xffffffffu, acc[nt][2], 1);
            float x3 = __shfl_xor_sync(0xffffffffu, acc[nt][3], 1);

            float F, I, A, O;
            if (!odd) { F = acc[nt][0]; I = acc[nt][1]; A = x0; O = x1; }
            else      { F = x2;         I = x3;         A = acc[nt][2]; O = acc[nt][3]; }

            F += gF[nt]; I += gI[nt]; A += gA[nt]; O += gO[nt];

            float f = sigf(F);
            float i = sigf(I);
            float a = tanhf(A);
            float o = sigf(O);

            float c = f * creg[nt] + i * a;
            creg[nt] = c;
            float h = o * tanhf(c);

            int j = jbase + nt * 2;
            hout[(size_t)bmy * HDIM + j] = __float2half(h);
            out[((size_t)bmy * TT + t) * HDIM + j] = h;
            if (t == TT - 1) {
                size_t qsz = (size_t)BB * TT * HDIM;
                out[qsz + (size_t)bmy * HDIM + j]             = h;
                out[qsz + BB * HDIM + (size_t)bmy * HDIM + j] = c;
            }
        }
    }
}

// ---------------------------------------------------------------------------
extern "C" void kernel_launch(void* const* d_in, const int* in_sizes, int n_in,
                              void* d_out, int out_size) {
    const float* x  = (const float*)d_in[0];
    const float* Wi = (const float*)d_in[1];
    const float* bi = (const float*)d_in[2];
    const float* Wh = (const float*)d_in[3];
    const float* bh = (const float*)d_in[4];
    float* out = (float*)d_out;

    const int smem_bytes = 65536 + 2 * 4 * SUBSZ * 2;   // 139,264 B
    cudaFuncSetAttribute(lstm_persist_kernel,
                         cudaFuncAttributeMaxDynamicSharedMemorySize, smem_bytes);

    gemm_tc_kernel<<<dim3(G4 / 128, (BB * TT) / 128), 256>>>(x, Wi, bi, bh);
    lstm_persist_kernel<<<GRID, 256, smem_bytes>>>(Wh, out);
}

// round 13
// speedup vs baseline: 1.2185x; 1.1435x over previous
#include <cuda_runtime.h>
#include <cuda_fp16.h>
#include <math.h>
#include <stdint.h>

#define BB    64
#define TT    256
#define IDIM  512
#define HDIM  1024
#define G4    4096        // 4*HDIM
#define GRID  128         // persistent blocks (<=148, all resident)
#define HROW  72          // padded sub-buffer row stride in halfs (64 data + 8 pad)
#define SUBSZ (64 * HROW) // halfs per 64x64 sub-buffer
#define CKB   256         // staging chunk width in halfs (4 sub-buffers)

#define APAD  40          // gemm As row stride in halfs (32 data + 8 pad)
#define BPAD  136         // gemm Bs row stride in halfs (128 data + 8 pad)

// ---- device scratch ----
__device__ float    g_gates[(size_t)TT * BB * G4];  // [T][B][4H], bi+bh folded in
__device__ __half   g_h[2][BB * HDIM];              // double-buffered hidden state
__device__ unsigned g_arrive;
__device__ unsigned g_gen;

// ---------------------------------------------------------------------------
// helpers
// ---------------------------------------------------------------------------
__device__ __forceinline__ void mma_f16(float d[4],
    uint32_t a0, uint32_t a1, uint32_t a2, uint32_t a3,
    uint32_t b0, uint32_t b1)
{
    asm volatile(
        "mma.sync.aligned.m16n8k16.row.col.f32.f16.f16.f32 "
        "{%0,%1,%2,%3},{%4,%5,%6,%7},{%8,%9},{%0,%1,%2,%3};\n"
        : "+f"(d[0]), "+f"(d[1]), "+f"(d[2]), "+f"(d[3])
        : "r"(a0), "r"(a1), "r"(a2), "r"(a3), "r"(b0), "r"(b1));
}

__device__ __forceinline__ void ldsm_x4(uint32_t& r0, uint32_t& r1,
                                        uint32_t& r2, uint32_t& r3,
                                        uint32_t smem_addr)
{
    asm volatile(
        "ldmatrix.sync.aligned.m8n8.x4.shared.b16 {%0,%1,%2,%3}, [%4];"
        : "=r"(r0), "=r"(r1), "=r"(r2), "=r"(r3)
        : "r"(smem_addr));
}

__device__ __forceinline__ void ldsm_x2_trans(uint32_t& r0, uint32_t& r1,
                                              uint32_t smem_addr)
{
    asm volatile(
        "ldmatrix.sync.aligned.m8n8.x2.trans.shared.b16 {%0,%1}, [%2];"
        : "=r"(r0), "=r"(r1)
        : "r"(smem_addr));
}

__device__ __forceinline__ float sigf(float x) {
    return 1.f / (1.f + __expf(-x));
}

// ---------------------------------------------------------------------------
// Phase 1: gates = x @ Wi + bi + bh   (M=16384, K=512, N=4096)  -- fp16 MMA
// 128x128 block tile, BK=32, 8 warps (2m x 4n), warp tile 64x32 (4x4 mma k16).
// A: row-major fp16 smem, frags via LDSM.x4 (persist-proven recipe).
// B: k-major fp16 smem, frags via LDSM.x2.trans.
// Register double-buffered global loads. Block (0,0) resets barrier state.
// ---------------------------------------------------------------------------
__global__ void __launch_bounds__(256, 2) gemm_f16_kernel(
    const float* __restrict__ X,   // [16384, 512]
    const float* __restrict__ Wi,  // [512, 4096]
    const float* __restrict__ bi,  // [4096]
    const float* __restrict__ bh)  // [4096]
{
    if (blockIdx.x == 0 && blockIdx.y == 0 && threadIdx.x == 0) {
        g_arrive = 0u;
        g_gen    = 0u;
    }

    __shared__ __half As[128][APAD];   // [m][k], row-major
    __shared__ __half Bs[32][BPAD];    // [k][n], k-major

    const int tid  = threadIdx.x;
    const int lane = tid & 31;
    const int w    = tid >> 5;
    const int wm   = w & 1;          // 0..1 (64 rows)
    const int wn   = w >> 1;         // 0..3 (32 cols)
    const int m0   = blockIdx.y * 128;
    const int n0   = blockIdx.x * 128;

    const int rowg = lane >> 2;      // 0..7
    const int kq   = lane & 3;       // 0..3

    // loader indices
    const int aRow = tid >> 1;            // 0..127
    const int aKh  = (tid & 1) * 16;      // 0 or 16 (halfs)
    const int bK   = tid >> 5;            // 0..7 (k rows, +8,+16,+24)
    const int bN   = (tid & 31) * 4;      // 0..124 (halfs)

    float acc[4][4][4];
#pragma unroll
    for (int mi = 0; mi < 4; mi++)
#pragma unroll
        for (int ni = 0; ni < 4; ni++)
#pragma unroll
            for (int q = 0; q < 4; q++) acc[mi][ni][q] = 0.f;

    // LDSM base addresses
    const uint32_t asB = (uint32_t)__cvta_generic_to_shared(&As[0][0]);
    const uint32_t bsB = (uint32_t)__cvta_generic_to_shared(&Bs[0][0]);

    // prefetch k-tile 0
    float4 pa[4], pb[4];
#pragma unroll
    for (int i = 0; i < 4; i++)
        pa[i] = *(const float4*)(X + (size_t)(m0 + aRow) * IDIM + aKh + i * 4);
#pragma unroll
    for (int h = 0; h < 4; h++)
        pb[h] = *(const float4*)(Wi + (size_t)(bK + h * 8) * G4 + n0 + bN);

    for (int k0 = 0; k0 < IDIM; k0 += 32) {
        // stage A: 16 floats -> 16 halfs -> 2 uint4
        {
            __half2 q0 = __floats2half2_rn(pa[0].x, pa[0].y);
            __half2 q1 = __floats2half2_rn(pa[0].z, pa[0].w);
            __half2 q2 = __floats2half2_rn(pa[1].x, pa[1].y);
            __half2 q3 = __floats2half2_rn(pa[1].z, pa[1].w);
            uint4 v0;
            v0.x = *(uint32_t*)&q0; v0.y = *(uint32_t*)&q1;
            v0.z = *(uint32_t*)&q2; v0.w = *(uint32_t*)&q3;
            *(uint4*)(&As[aRow][aKh]) = v0;
            q0 = __floats2half2_rn(pa[2].x, pa[2].y);
            q1 = __floats2half2_rn(pa[2].z, pa[2].w);
            q2 = __floats2half2_rn(pa[3].x, pa[3].y);
            q3 = __floats2half2_rn(pa[3].z, pa[3].w);
            uint4 v1;
            v1.x = *(uint32_t*)&q0; v1.y = *(uint32_t*)&q1;
            v1.z = *(uint32_t*)&q2; v1.w = *(uint32_t*)&q3;
            *(uint4*)(&As[aRow][aKh + 8]) = v1;
        }
        // stage B: per k row, 4 floats -> 4 halfs (8B)
#pragma unroll
        for (int h = 0; h < 4; h++) {
            __half2 q0 = __floats2half2_rn(pb[h].x, pb[h].y);
            __half2 q1 = __floats2half2_rn(pb[h].z, pb[h].w);
            uint2 v;
            v.x = *(uint32_t*)&q0; v.y = *(uint32_t*)&q1;
            *(uint2*)(&Bs[bK + h * 8][bN]) = v;
        }
        __syncthreads();

        // prefetch next k-tile
        if (k0 + 32 < IDIM) {
            int kn = k0 + 32;
#pragma unroll
            for (int i = 0; i < 4; i++)
                pa[i] = *(const float4*)(X + (size_t)(m0 + aRow) * IDIM + kn + aKh + i * 4);
#pragma unroll
            for (int h = 0; h < 4; h++)
                pb[h] = *(const float4*)(Wi + (size_t)(kn + bK + h * 8) * G4 + n0 + bN);
        }

        // 2 k16 steps of fp16 mma
#pragma unroll
        for (int ks = 0; ks < 2; ks++) {
            uint32_t af[4][4], bf[4][2];
#pragma unroll
            for (int mi = 0; mi < 4; mi++) {
                uint32_t addr = asB
                    + (uint32_t)((wm * 64 + mi * 16 + (lane & 15)) * APAD * 2)
                    + (uint32_t)(ks * 32) + ((lane & 16) ? 16u : 0u);
                ldsm_x4(af[mi][0], af[mi][1], af[mi][2], af[mi][3], addr);
            }
#pragma unroll
            for (int ni = 0; ni < 4; ni++) {
                uint32_t addr = bsB
                    + (uint32_t)((ks * 16 + (lane & 15)) * BPAD * 2)
                    + (uint32_t)((wn * 32 + ni * 8) * 2);
                ldsm_x2_trans(bf[ni][0], bf[ni][1], addr);
            }
#pragma unroll
            for (int mi = 0; mi < 4; mi++)
#pragma unroll
                for (int ni = 0; ni < 4; ni++)
                    mma_f16(acc[mi][ni], af[mi][0], af[mi][1], af[mi][2], af[mi][3],
                            bf[ni][0], bf[ni][1]);
        }
        __syncthreads();
    }

    // epilogue -> g_gates[t][b][n]  (D-frag layout identical to tf32 version)
#pragma unroll
    for (int ni = 0; ni < 4; ni++) {
        int n = n0 + wn * 32 + ni * 8 + 2 * kq;
        float bias0 = bi[n] + bh[n];
        float bias1 = bi[n + 1] + bh[n + 1];
#pragma unroll
        for (int mi = 0; mi < 4; mi++) {
            int m  = m0 + wm * 64 + mi * 16 + rowg;
            {
                int b = m >> 8, t = m & 255;
                float2 v = make_float2(acc[mi][ni][0] + bias0, acc[mi][ni][1] + bias1);
                *(float2*)(g_gates + (size_t)(t * BB + b) * G4 + n) = v;
            }
            {
                int m2 = m + 8;
                int b = m2 >> 8, t = m2 & 255;
                float2 v = make_float2(acc[mi][ni][2] + bias0, acc[mi][ni][3] + bias1);
                *(float2*)(g_gates + (size_t)(t * BB + b) * G4 + n) = v;
            }
        }
    }
}

// ---------------------------------------------------------------------------
// Phase 2: persistent LSTM recurrence -- byte-identical to R12 (proven).
// ---------------------------------------------------------------------------
__global__ void __launch_bounds__(256, 1) lstm_persist_kernel(
    const float* __restrict__ Wh,   // [1024, 4096]
    float* __restrict__ out)        // Q_all | hT | cT
{
    extern __shared__ char smem[];
    uint4*  Wfq = (uint4*)smem;                      // [64 s][2 wn][32 lanes] = 64 KB
    __half* Hs  = (__half*)(smem + 65536);           // 2 * 4 * SUBSZ halfs

    const int tid  = threadIdx.x;
    const int lane = tid & 31;
    const int wid  = tid >> 5;
    const int wm   = wid & 3;
    const int wn   = wid >> 2;
    const int bx   = blockIdx.x;

    for (int e = tid; e < 64 * 2 * 32; e += 256) {
        int l  = e & 31;
        int w2 = (e >> 5) & 1;
        int s  = e >> 6;
        int k  = s * 16 + (l & 3) * 2;
        uint32_t vals[4];
#pragma unroll
        for (int nt = 0; nt < 2; nt++) {
            int ct = w2 * 2 + nt;
            int n  = ct * 8 + (l >> 2);
            int j  = bx * 8 + (n >> 2);
            int g  = n & 3;
            const float* Wcol = Wh + (size_t)g * 1024 + j;
            __half2 h0 = __floats2half2_rn(Wcol[(size_t)k * G4],
                                           Wcol[(size_t)(k + 1) * G4]);
            __half2 h1 = __floats2half2_rn(Wcol[(size_t)(k + 8) * G4],
                                           Wcol[(size_t)(k + 9) * G4]);
            vals[nt * 2]     = *(uint32_t*)&h0;
            vals[nt * 2 + 1] = *(uint32_t*)&h1;
        }
        Wfq[e] = make_uint4(vals[0], vals[1], vals[2], vals[3]);
    }
    __syncthreads();

    const int kq   = lane & 3;
    const int rowg = lane >> 2;
    const int odd  = lane & 1;
    const int bmy  = wm * 16 + rowg + (odd ? 8 : 0);
    const int jbase = bx * 8 + wn * 4 + (kq >> 1);

    float creg[2] = {0.f, 0.f};

    const uint32_t hsB = (uint32_t)__cvta_generic_to_shared(Hs);
    const uint32_t laneA = hsB
        + (uint32_t)((wm * 16 + (lane & 15)) * HROW) * 2
        + ((lane & 16) ? 16u : 0u);

    const int sb = tid >> 3;
    const int sg = tid & 7;

    for (int t = 0; t < TT; t++) {
        float acc[2][4] = {{0.f,0.f,0.f,0.f},{0.f,0.f,0.f,0.f}};

        const float* __restrict__ gt = g_gates + (size_t)t * BB * G4;
        float gF[2], gI[2], gA[2], gO[2];
#pragma unroll
        for (int nt = 0; nt < 2; nt++) {
            int j = jbase + nt * 2;
            gF[nt] = __ldcg(gt + (size_t)bmy * G4 + j);
            gI[nt] = __ldcg(gt + (size_t)bmy * G4 + 1024 + j);
            gA[nt] = __ldcg(gt + (size_t)bmy * G4 + 2048 + j);
            gO[nt] = __ldcg(gt + (size_t)bmy * G4 + 3072 + j);
        }

        if (t > 0) {
            __threadfence();
            __syncthreads();
            if (tid == 0) {
                unsigned a = atomicAdd(&g_arrive, 1u);
                if (a == GRID - 1u) {
                    g_arrive = 0u;
                    __threadfence();
                    atomicExch(&g_gen, (unsigned)t);
                } else {
                    while (atomicAdd(&g_gen, 0u) < (unsigned)t) { }
                }
            }
            __syncthreads();

            const __half* __restrict__ hin = g_h[t & 1];

            uint4 pf[2][4];
#pragma unroll
            for (int i = 0; i < 2; i++) {
                int b = sb + i * 32;
#pragma unroll
                for (int q = 0; q < 4; q++)
                    pf[i][q] = __ldcg((const uint4*)(hin + (size_t)b * HDIM
                                                     + q * 64 + sg * 8));
            }

            int buf = 0;
            for (int ch = 0; ch < 4; ch++) {
                {
                    __half* H = Hs + buf * (4 * SUBSZ);
#pragma unroll
                    for (int i = 0; i < 2; i++) {
                        int b = sb + i * 32;
#pragma unroll
                        for (int q = 0; q < 4; q++)
                            *(uint4*)(H + q * SUBSZ + b * HROW + sg * 8) = pf[i][q];
                    }
                }
                __syncthreads();

                if (ch < 3) {
                    int k0 = (ch + 1) * CKB;
#pragma unroll
                    for (int i = 0; i < 2; i++) {
                        int b = sb + i * 32;
#pragma unroll
                        for (int q = 0; q < 4; q++)
                            pf[i][q] = __ldcg((const uint4*)(hin + (size_t)b * HDIM
                                                             + k0 + q * 64 + sg * 8));
                    }
                }

                const uint32_t chunkA = laneA + (uint32_t)(buf * (4 * SUBSZ * 2));
#pragma unroll
                for (int ks = 0; ks < 16; ks++) {
                    int q   = ks >> 2;
                    int kss = ks & 3;
                    uint32_t a0, a1, a2, a3;
                    ldsm_x4(a0, a1, a2, a3,
                            chunkA + (uint32_t)(q * (SUBSZ * 2) + kss * 32));
                    int s = ch * 16 + ks;
                    uint4 bv = Wfq[(s * 2 + wn) * 32 + lane];
                    mma_f16(acc[0], a0, a1, a2, a3, bv.x, bv.y);
                    mma_f16(acc[1], a0, a1, a2, a3, bv.z, bv.w);
                }
                buf ^= 1;
            }
            __syncthreads();
        }

        __half* __restrict__ hout = g_h[(t + 1) & 1];
#pragma unroll
        for (int nt = 0; nt < 2; nt++) {
            float x0 = __shfl_xor_sync(0xffffffffu, acc[nt][0], 1);
            float x1 = __shfl_xor_sync(0xffffffffu, acc[nt][1], 1);
            float x2 = __shfl_xor_sync(0xffffffffu, acc[nt][2], 1);
            float x3 = __shfl_xor_sync(0xffffffffu, acc[nt][3], 1);

            float F, I, A, O;
            if (!odd) { F = acc[nt][0]; I = acc[nt][1]; A = x0; O = x1; }
            else      { F = x2;         I = x3;         A = acc[nt][2]; O = acc[nt][3]; }

            F += gF[nt]; I += gI[nt]; A += gA[nt]; O += gO[nt];

            float f = sigf(F);
            float i = sigf(I);
            float a = tanhf(A);
            float o = sigf(O);

            float c = f * creg[nt] + i * a;
            creg[nt] = c;
            float h = o * tanhf(c);

            int j = jbase + nt * 2;
            hout[(size_t)bmy * HDIM + j] = __float2half(h);
            out[((size_t)bmy * TT + t) * HDIM + j] = h;
            if (t == TT - 1) {
                size_t qsz = (size_t)BB * TT * HDIM;
                out[qsz + (size_t)bmy * HDIM + j]             = h;
                out[qsz + BB * HDIM + (size_t)bmy * HDIM + j] = c;
            }
        }
    }
}

// ---------------------------------------------------------------------------
extern "C" void kernel_launch(void* const* d_in, const int* in_sizes, int n_in,
                              void* d_out, int out_size) {
    const float* x  = (const float*)d_in[0];
    const float* Wi = (const float*)d_in[1];
    const float* bi = (const float*)d_in[2];
    const float* Wh = (const float*)d_in[3];
    const float* bh = (const float*)d_in[4];
    float* out = (float*)d_out;

    const int smem_bytes = 65536 + 2 * 4 * SUBSZ * 2;   // 139,264 B
    cudaFuncSetAttribute(lstm_persist_kernel,
                         cudaFuncAttributeMaxDynamicSharedMemorySize, smem_bytes);

    gemm_f16_kernel<<<dim3(G4 / 128, (BB * TT) / 128), 256>>>(x, Wi, bi, bh);
    lstm_persist_kernel<<<GRID, 256, smem_bytes>>>(Wh, out);
}

// round 14
// speedup vs baseline: 1.2993x; 1.0663x over previous
#include <cuda_runtime.h>
#include <cuda_fp16.h>
#include <math.h>
#include <stdint.h>

#define BB    64
#define TT    256
#define IDIM  512
#define HDIM  1024
#define G4    4096        // 4*HDIM
#define GRID  128         // persistent blocks (<=148, all resident)
#define HROW  72          // padded sub-buffer row stride in halfs (64 data + 8 pad)
#define SUBSZ (64 * HROW) // halfs per 64x64 sub-buffer
#define CKB   256         // staging chunk width in halfs (4 sub-buffers)

#define APAD  40          // gemm As row stride in halfs (32 data + 8 pad)
#define BPAD  136         // gemm Bs row stride in halfs (128 data + 8 pad)

#define NGRP  8           // barrier groups (16 blocks each)

// ---- device scratch ----
__device__ float    g_gates[(size_t)TT * BB * G4];  // [T][B][4H], bi+bh folded in
__device__ __half   g_h[2][BB * HDIM];              // double-buffered hidden state
__device__ unsigned g_cnt[NGRP * 32];               // barrier counters, 128B apart

// ---------------------------------------------------------------------------
// helpers
// ---------------------------------------------------------------------------
__device__ __forceinline__ void mma_f16(float d[4],
    uint32_t a0, uint32_t a1, uint32_t a2, uint32_t a3,
    uint32_t b0, uint32_t b1)
{
    asm volatile(
        "mma.sync.aligned.m16n8k16.row.col.f32.f16.f16.f32 "
        "{%0,%1,%2,%3},{%4,%5,%6,%7},{%8,%9},{%0,%1,%2,%3};\n"
        : "+f"(d[0]), "+f"(d[1]), "+f"(d[2]), "+f"(d[3])
        : "r"(a0), "r"(a1), "r"(a2), "r"(a3), "r"(b0), "r"(b1));
}

__device__ __forceinline__ void ldsm_x4(uint32_t& r0, uint32_t& r1,
                                        uint32_t& r2, uint32_t& r3,
                                        uint32_t smem_addr)
{
    asm volatile(
        "ldmatrix.sync.aligned.m8n8.x4.shared.b16 {%0,%1,%2,%3}, [%4];"
        : "=r"(r0), "=r"(r1), "=r"(r2), "=r"(r3)
        : "r"(smem_addr));
}

__device__ __forceinline__ void ldsm_x2_trans(uint32_t& r0, uint32_t& r1,
                                              uint32_t smem_addr)
{
    asm volatile(
        "ldmatrix.sync.aligned.m8n8.x2.trans.shared.b16 {%0,%1}, [%2];"
        : "=r"(r0), "=r"(r1)
        : "r"(smem_addr));
}

__device__ __forceinline__ float sigf(float x) {
    return 1.f / (1.f + __expf(-x));
}

// ---------------------------------------------------------------------------
// Phase 1: gates = x @ Wi + bi + bh   (fp16 MMA, unchanged from R13/proven)
// Block (0,0) zeroes the barrier counters (stream order protects persist).
// ---------------------------------------------------------------------------
__global__ void __launch_bounds__(256, 2) gemm_f16_kernel(
    const float* __restrict__ X,   // [16384, 512]
    const float* __restrict__ Wi,  // [512, 4096]
    const float* __restrict__ bi,  // [4096]
    const float* __restrict__ bh)  // [4096]
{
    if (blockIdx.x == 0 && blockIdx.y == 0 && threadIdx.x < NGRP)
        g_cnt[threadIdx.x * 32] = 0u;

    __shared__ __half As[128][APAD];   // [m][k], row-major
    __shared__ __half Bs[32][BPAD];    // [k][n], k-major

    const int tid  = threadIdx.x;
    const int lane = tid & 31;
    const int w    = tid >> 5;
    const int wm   = w & 1;
    const int wn   = w >> 1;
    const int m0   = blockIdx.y * 128;
    const int n0   = blockIdx.x * 128;

    const int rowg = lane >> 2;
    const int kq   = lane & 3;

    const int aRow = tid >> 1;
    const int aKh  = (tid & 1) * 16;
    const int bK   = tid >> 5;
    const int bN   = (tid & 31) * 4;

    float acc[4][4][4];
#pragma unroll
    for (int mi = 0; mi < 4; mi++)
#pragma unroll
        for (int ni = 0; ni < 4; ni++)
#pragma unroll
            for (int q = 0; q < 4; q++) acc[mi][ni][q] = 0.f;

    const uint32_t asB = (uint32_t)__cvta_generic_to_shared(&As[0][0]);
    const uint32_t bsB = (uint32_t)__cvta_generic_to_shared(&Bs[0][0]);

    float4 pa[4], pb[4];
#pragma unroll
    for (int i = 0; i < 4; i++)
        pa[i] = *(const float4*)(X + (size_t)(m0 + aRow) * IDIM + aKh + i * 4);
#pragma unroll
    for (int h = 0; h < 4; h++)
        pb[h] = *(const float4*)(Wi + (size_t)(bK + h * 8) * G4 + n0 + bN);

    for (int k0 = 0; k0 < IDIM; k0 += 32) {
        {
            __half2 q0 = __floats2half2_rn(pa[0].x, pa[0].y);
            __half2 q1 = __floats2half2_rn(pa[0].z, pa[0].w);
            __half2 q2 = __floats2half2_rn(pa[1].x, pa[1].y);
            __half2 q3 = __floats2half2_rn(pa[1].z, pa[1].w);
            uint4 v0;
            v0.x = *(uint32_t*)&q0; v0.y = *(uint32_t*)&q1;
            v0.z = *(uint32_t*)&q2; v0.w = *(uint32_t*)&q3;
            *(uint4*)(&As[aRow][aKh]) = v0;
            q0 = __floats2half2_rn(pa[2].x, pa[2].y);
            q1 = __floats2half2_rn(pa[2].z, pa[2].w);
            q2 = __floats2half2_rn(pa[3].x, pa[3].y);
            q3 = __floats2half2_rn(pa[3].z, pa[3].w);
            uint4 v1;
            v1.x = *(uint32_t*)&q0; v1.y = *(uint32_t*)&q1;
            v1.z = *(uint32_t*)&q2; v1.w = *(uint32_t*)&q3;
            *(uint4*)(&As[aRow][aKh + 8]) = v1;
        }
#pragma unroll
        for (int h = 0; h < 4; h++) {
            __half2 q0 = __floats2half2_rn(pb[h].x, pb[h].y);
            __half2 q1 = __floats2half2_rn(pb[h].z, pb[h].w);
            uint2 v;
            v.x = *(uint32_t*)&q0; v.y = *(uint32_t*)&q1;
            *(uint2*)(&Bs[bK + h * 8][bN]) = v;
        }
        __syncthreads();

        if (k0 + 32 < IDIM) {
            int kn = k0 + 32;
#pragma unroll
            for (int i = 0; i < 4; i++)
                pa[i] = *(const float4*)(X + (size_t)(m0 + aRow) * IDIM + kn + aKh + i * 4);
#pragma unroll
            for (int h = 0; h < 4; h++)
                pb[h] = *(const float4*)(Wi + (size_t)(kn + bK + h * 8) * G4 + n0 + bN);
        }

#pragma unroll
        for (int ks = 0; ks < 2; ks++) {
            uint32_t af[4][4], bf[4][2];
#pragma unroll
            for (int mi = 0; mi < 4; mi++) {
                uint32_t addr = asB
                    + (uint32_t)((wm * 64 + mi * 16 + (lane & 15)) * APAD * 2)
                    + (uint32_t)(ks * 32) + ((lane & 16) ? 16u : 0u);
                ldsm_x4(af[mi][0], af[mi][1], af[mi][2], af[mi][3], addr);
            }
#pragma unroll
            for (int ni = 0; ni < 4; ni++) {
                uint32_t addr = bsB
                    + (uint32_t)((ks * 16 + (lane & 15)) * BPAD * 2)
                    + (uint32_t)((wn * 32 + ni * 8) * 2);
                ldsm_x2_trans(bf[ni][0], bf[ni][1], addr);
            }
#pragma unroll
            for (int mi = 0; mi < 4; mi++)
#pragma unroll
                for (int ni = 0; ni < 4; ni++)
                    mma_f16(acc[mi][ni], af[mi][0], af[mi][1], af[mi][2], af[mi][3],
                            bf[ni][0], bf[ni][1]);
        }
        __syncthreads();
    }

#pragma unroll
    for (int ni = 0; ni < 4; ni++) {
        int n = n0 + wn * 32 + ni * 8 + 2 * kq;
        float bias0 = bi[n] + bh[n];
        float bias1 = bi[n + 1] + bh[n + 1];
#pragma unroll
        for (int mi = 0; mi < 4; mi++) {
            int m  = m0 + wm * 64 + mi * 16 + rowg;
            {
                int b = m >> 8, t = m & 255;
                float2 v = make_float2(acc[mi][ni][0] + bias0, acc[mi][ni][1] + bias1);
                *(float2*)(g_gates + (size_t)(t * BB + b) * G4 + n) = v;
            }
            {
                int m2 = m + 8;
                int b = m2 >> 8, t = m2 & 255;
                float2 v = make_float2(acc[mi][ni][2] + bias0, acc[mi][ni][3] + bias1);
                *(float2*)(g_gates + (size_t)(t * BB + b) * G4 + n) = v;
            }
        }
    }
}

// ---------------------------------------------------------------------------
// Phase 2: persistent LSTM recurrence (R13 skeleton).
// ONLY change: grid barrier arrive/release.
//   arrive  = red.release.gpu.add to 1 of 8 line-padded group counters
//             (16x less L2-atomic serialization, no central g_gen hop)
//   release = warp-0 lanes 0..7 acquire-poll their counter for epoch 16*t
//             (independent scalar spins + nanosleep; no warp collectives)
// Monotonic epochs -> no reset race; counters zeroed by gemm each replay.
// ---------------------------------------------------------------------------
__global__ void __launch_bounds__(256, 1) lstm_persist_kernel(
    const float* __restrict__ Wh,   // [1024, 4096]
    float* __restrict__ out)        // Q_all | hT | cT
{
    extern __shared__ char smem[];
    uint4*  Wfq = (uint4*)smem;                      // [64 s][2 wn][32 lanes] = 64 KB
    __half* Hs  = (__half*)(smem + 65536);           // 2 * 4 * SUBSZ halfs

    const int tid  = threadIdx.x;
    const int lane = tid & 31;
    const int wid  = tid >> 5;
    const int wm   = wid & 3;
    const int wn   = wid >> 2;
    const int bx   = blockIdx.x;

    for (int e = tid; e < 64 * 2 * 32; e += 256) {
        int l  = e & 31;
        int w2 = (e >> 5) & 1;
        int s  = e >> 6;
        int k  = s * 16 + (l & 3) * 2;
        uint32_t vals[4];
#pragma unroll
        for (int nt = 0; nt < 2; nt++) {
            int ct = w2 * 2 + nt;
            int n  = ct * 8 + (l >> 2);
            int j  = bx * 8 + (n >> 2);
            int g  = n & 3;
            const float* Wcol = Wh + (size_t)g * 1024 + j;
            __half2 h0 = __floats2half2_rn(Wcol[(size_t)k * G4],
                                           Wcol[(size_t)(k + 1) * G4]);
            __half2 h1 = __floats2half2_rn(Wcol[(size_t)(k + 8) * G4],
                                           Wcol[(size_t)(k + 9) * G4]);
            vals[nt * 2]     = *(uint32_t*)&h0;
            vals[nt * 2 + 1] = *(uint32_t*)&h1;
        }
        Wfq[e] = make_uint4(vals[0], vals[1], vals[2], vals[3]);
    }
    __syncthreads();

    const int kq   = lane & 3;
    const int rowg = lane >> 2;
    const int odd  = lane & 1;
    const int bmy  = wm * 16 + rowg + (odd ? 8 : 0);
    const int jbase = bx * 8 + wn * 4 + (kq >> 1);

    float creg[2] = {0.f, 0.f};

    const uint32_t hsB = (uint32_t)__cvta_generic_to_shared(Hs);
    const uint32_t laneA = hsB
        + (uint32_t)((wm * 16 + (lane & 15)) * HROW) * 2
        + ((lane & 16) ? 16u : 0u);

    const int sb = tid >> 3;
    const int sg = tid & 7;

    unsigned* const my_cnt = &g_cnt[(bx >> 4) * 32];

    for (int t = 0; t < TT; t++) {
        float acc[2][4] = {{0.f,0.f,0.f,0.f},{0.f,0.f,0.f,0.f}};

        const float* __restrict__ gt = g_gates + (size_t)t * BB * G4;
        float gF[2], gI[2], gA[2], gO[2];
#pragma unroll
        for (int nt = 0; nt < 2; nt++) {
            int j = jbase + nt * 2;
            gF[nt] = __ldcg(gt + (size_t)bmy * G4 + j);
            gI[nt] = __ldcg(gt + (size_t)bmy * G4 + 1024 + j);
            gA[nt] = __ldcg(gt + (size_t)bmy * G4 + 2048 + j);
            gO[nt] = __ldcg(gt + (size_t)bmy * G4 + 3072 + j);
        }

        if (t > 0) {
            // ---- grid barrier: distributed arrive + direct poll ----
            __threadfence();
            __syncthreads();
            if (wid == 0) {
                if (lane == 0)
                    asm volatile("red.release.gpu.global.add.u32 [%0], %1;"
                                 :: "l"(my_cnt), "r"(1u) : "memory");
                if (lane < NGRP) {
                    const unsigned* p = &g_cnt[lane * 32];
                    const unsigned target = (unsigned)t * (GRID / NGRP);
                    unsigned v;
                    for (;;) {
                        asm volatile("ld.global.acquire.gpu.u32 %0, [%1];"
                                     : "=r"(v) : "l"(p) : "memory");
                        if (v >= target) break;
                        __nanosleep(64);
                    }
                }
            }
            __syncthreads();

            const __half* __restrict__ hin = g_h[t & 1];

            uint4 pf[2][4];
#pragma unroll
            for (int i = 0; i < 2; i++) {
                int b = sb + i * 32;
#pragma unroll
                for (int q = 0; q < 4; q++)
                    pf[i][q] = __ldcg((const uint4*)(hin + (size_t)b * HDIM
                                                     + q * 64 + sg * 8));
            }

            int buf = 0;
            for (int ch = 0; ch < 4; ch++) {
                {
                    __half* H = Hs + buf * (4 * SUBSZ);
#pragma unroll
                    for (int i = 0; i < 2; i++) {
                        int b = sb + i * 32;
#pragma unroll
                        for (int q = 0; q < 4; q++)
                            *(uint4*)(H + q * SUBSZ + b * HROW + sg * 8) = pf[i][q];
                    }
                }
                __syncthreads();

                if (ch < 3) {
                    int k0 = (ch + 1) * CKB;
#pragma unroll
                    for (int i = 0; i < 2; i++) {
                        int b = sb + i * 32;
#pragma unroll
                        for (int q = 0; q < 4; q++)
                            pf[i][q] = __ldcg((const uint4*)(hin + (size_t)b * HDIM
                                                             + k0 + q * 64 + sg * 8));
                    }
                }

                const uint32_t chunkA = laneA + (uint32_t)(buf * (4 * SUBSZ * 2));
#pragma unroll
                for (int ks = 0; ks < 16; ks++) {
                    int q   = ks >> 2;
                    int kss = ks & 3;
                    uint32_t a0, a1, a2, a3;
                    ldsm_x4(a0, a1, a2, a3,
                            chunkA + (uint32_t)(q * (SUBSZ * 2) + kss * 32));
                    int s = ch * 16 + ks;
                    uint4 bv = Wfq[(s * 2 + wn) * 32 + lane];
                    mma_f16(acc[0], a0, a1, a2, a3, bv.x, bv.y);
                    mma_f16(acc[1], a0, a1, a2, a3, bv.z, bv.w);
                }
                buf ^= 1;
            }
            __syncthreads();
        }

        __half* __restrict__ hout = g_h[(t + 1) & 1];
#pragma unroll
        for (int nt = 0; nt < 2; nt++) {
            float x0 = __shfl_xor_sync(0xffffffffu, acc[nt][0], 1);
            float x1 = __shfl_xor_sync(0xffffffffu, acc[nt][1], 1);
            float x2 = __shfl_xor_sync(0xffffffffu, acc[nt][2], 1);
            float x3 = __shfl_xor_sync(0xffffffffu, acc[nt][3], 1);

            float F, I, A, O;
            if (!odd) { F = acc[nt][0]; I = acc[nt][1]; A = x0; O = x1; }
            else      { F = x2;         I = x3;         A = acc[nt][2]; O = acc[nt][3]; }

            F += gF[nt]; I += gI[nt]; A += gA[nt]; O += gO[nt];

            float f = sigf(F);
            float i = sigf(I);
            float a = tanhf(A);
            float o = sigf(O);

            float c = f * creg[nt] + i * a;
            creg[nt] = c;
            float h = o * tanhf(c);

            int j = jbase + nt * 2;
            hout[(size_t)bmy * HDIM + j] = __float2half(h);
            out[((size_t)bmy * TT + t) * HDIM + j] = h;
            if (t == TT - 1) {
                size_t qsz = (size_t)BB * TT * HDIM;
                out[qsz + (size_t)bmy * HDIM + j]             = h;
                out[qsz + BB * HDIM + (size_t)bmy * HDIM + j] = c;
            }
        }
    }
}

// ---------------------------------------------------------------------------
extern "C" void kernel_launch(void* const* d_in, const int* in_sizes, int n_in,
                              void* d_out, int out_size) {
    const float* x  = (const float*)d_in[0];
    const float* Wi = (const float*)d_in[1];
    const float* bi = (const float*)d_in[2];
    const float* Wh = (const float*)d_in[3];
    const float* bh = (const float*)d_in[4];
    float* out = (float*)d_out;

    const int smem_bytes = 65536 + 2 * 4 * SUBSZ * 2;   // 139,264 B
    cudaFuncSetAttribute(lstm_persist_kernel,
                         cudaFuncAttributeMaxDynamicSharedMemorySize, smem_bytes);

    gemm_f16_kernel<<<dim3(G4 / 128, (BB * TT) / 128), 256>>>(x, Wi, bi, bh);
    lstm_persist_kernel<<<GRID, 256, smem_bytes>>>(Wh, out);
}